// round 6
// baseline (speedup 1.0000x reference)
#include <cuda_runtime.h>

#define N_NODES 50000
#define N_EDGES 500000
#define HID 128
#define EDIM 32

// ---------------- scratch (device globals: no allocation allowed) ----------------
__device__ float g_sum [N_NODES * HID];   // scatter-sum of encoded edges
__device__ float g_cnt [N_NODES];         // per-node edge counts
__device__ float g_hnew[N_NODES * HID];   // GRU output

// ---------------- zero scratch ----------------
__global__ void zero_k() {
    int i = blockIdx.x * blockDim.x + threadIdx.x;
    if (i < N_NODES * HID) g_sum[i] = 0.0f;
    if (i < N_NODES)       g_cnt[i] = 0.0f;
}

// ---------------- packed fp32x2 helpers (sm_100a FFMA2) ----------------
__device__ __forceinline__ unsigned long long fma2(unsigned long long a,
                                                   unsigned long long b,
                                                   unsigned long long c) {
    unsigned long long d;
    asm("fma.rn.f32x2 %0, %1, %2, %3;" : "=l"(d) : "l"(a), "l"(b), "l"(c));
    return d;
}
__device__ __forceinline__ void unpack2(unsigned long long v, float& lo, float& hi) {
    asm("mov.b64 {%0, %1}, %2;" : "=f"(lo), "=f"(hi) : "l"(v));
}

__device__ __forceinline__ float4 ldg4(const float* p) {
    return __ldg((const float4*)p);
}
__device__ __forceinline__ ulonglong2 ldg2x64(const float* p) {
    return __ldg((const ulonglong2*)p);
}

// LayerNorm(128) + affine + ReLU; lane holds channels lane*4..lane*4+3.
__device__ __forceinline__ float4 ln_relu(float4 v, float4 g, float4 b) {
    float s = v.x + v.y + v.z + v.w;
    float q = v.x * v.x + v.y * v.y + v.z * v.z + v.w * v.w;
#pragma unroll
    for (int o = 16; o > 0; o >>= 1) {
        s += __shfl_xor_sync(0xffffffffu, s, o);
        q += __shfl_xor_sync(0xffffffffu, q, o);
    }
    float mu   = s * (1.0f / 128.0f);
    float var  = q * (1.0f / 128.0f) - mu * mu;
    float rstd = rsqrtf(var + 1e-5f);
    float4 r;
    r.x = fmaxf((v.x - mu) * rstd * g.x + b.x, 0.0f);
    r.y = fmaxf((v.y - mu) * rstd * g.y + b.y, 0.0f);
    r.z = fmaxf((v.z - mu) * rstd * g.z + b.z, 0.0f);
    r.w = fmaxf((v.w - mu) * rstd * g.w + b.w, 0.0f);
    return r;
}

// 8 packed FMAs covering 4 k-rows x 4 output channels for one edge.
// A01/A23: duplicated activations (a0,a0),(a1,a1) / (a2,a2),(a3,a3)
// W0..W3: weight rows as ulonglong2 ((ch0,ch1),(ch2,ch3))
#define FMA2_STEP(AccA, AccB, A01, A23, W0, W1r, W2r, W3r)      \
    AccA = fma2(A01.x, W0.x,  AccA); AccB = fma2(A01.x, W0.y,  AccB); \
    AccA = fma2(A01.y, W1r.x, AccA); AccB = fma2(A01.y, W1r.y, AccB); \
    AccA = fma2(A23.x, W2r.x, AccA); AccB = fma2(A23.x, W2r.y, AccB); \
    AccA = fma2(A23.y, W3r.x, AccA); AccB = fma2(A23.y, W3r.y, AccB);

// ---------------- kernel 1: edge encoder (Lin-LN-ReLU x2) + scatter-add ----------
// block = 128 threads = 4 warps; 4 edges/warp; 16 edges/block.
// Activations stored DUPLICATED in smem so LDS.128 yields packed (a,a) pairs.
__global__ void __launch_bounds__(128) enc_scatter_k(
    const float* __restrict__ ea, const int* __restrict__ eidx,
    const float* __restrict__ W1, const float* __restrict__ b1,
    const float* __restrict__ g1, const float* __restrict__ be1,
    const float* __restrict__ W2, const float* __restrict__ b2,
    const float* __restrict__ g2, const float* __restrict__ be2)
{
    __shared__ float sEAd[16 * 2 * EDIM];        // duplicated edge_attr: 4 KB
    __shared__ float sH1d[4][4][2 * HID];        // duplicated hidden:   16 KB

    const int tid  = threadIdx.x;
    const int w    = tid >> 5;
    const int lane = tid & 31;
    const int ch   = lane * 4;
    const long base = (long)blockIdx.x * 16;

    // cooperative coalesced load of 16 edges x 32 attrs, stored duplicated
    {
        float4 v = ((const float4*)(ea + base * EDIM))[tid];
        float* dp = sEAd + tid * 8;              // 8 floats per source float4
        *(float4*)(dp)     = make_float4(v.x, v.x, v.y, v.y);
        *(float4*)(dp + 4) = make_float4(v.z, v.z, v.w, v.w);
    }
    __syncthreads();

    // ---- layer 1: [4 edges,32] @ W1[32,128] ----
    unsigned long long aA[4], aB[4];
#pragma unroll
    for (int e = 0; e < 4; ++e) { aA[e] = 0ull; aB[e] = 0ull; }

#pragma unroll
    for (int i4 = 0; i4 < EDIM / 4; ++i4) {
        const float* wp = W1 + (i4 * 4) * HID + ch;
        ulonglong2 w0  = ldg2x64(wp);
        ulonglong2 w1r = ldg2x64(wp + HID);
        ulonglong2 w2r = ldg2x64(wp + 2 * HID);
        ulonglong2 w3r = ldg2x64(wp + 3 * HID);
#pragma unroll
        for (int e = 0; e < 4; ++e) {
            const float* ap = sEAd + (w * 4 + e) * (2 * EDIM) + i4 * 8;
            ulonglong2 a01 = *(const ulonglong2*)(ap);
            ulonglong2 a23 = *(const ulonglong2*)(ap + 4);
            FMA2_STEP(aA[e], aB[e], a01, a23, w0, w1r, w2r, w3r)
        }
    }

    float4 b1v  = ldg4(b1 + ch);
    float4 g1v  = ldg4(g1 + ch);
    float4 be1v = ldg4(be1 + ch);
#pragma unroll
    for (int e = 0; e < 4; ++e) {
        float4 v;
        unpack2(aA[e], v.x, v.y);
        unpack2(aB[e], v.z, v.w);
        v.x += b1v.x; v.y += b1v.y; v.z += b1v.z; v.w += b1v.w;
        float4 o = ln_relu(v, g1v, be1v);
        float* dp = &sH1d[w][e][2 * ch];
        *(float4*)(dp)     = make_float4(o.x, o.x, o.y, o.y);
        *(float4*)(dp + 4) = make_float4(o.z, o.z, o.w, o.w);
    }
    __syncwarp();

    // ---- layer 2: [4 edges,128] @ W2[128,128] ----
    unsigned long long cA[4], cB[4];
#pragma unroll
    for (int e = 0; e < 4; ++e) { cA[e] = 0ull; cB[e] = 0ull; }

#pragma unroll 8
    for (int i4 = 0; i4 < HID / 4; ++i4) {
        const float* wp = W2 + (i4 * 4) * HID + ch;
        ulonglong2 w0  = ldg2x64(wp);
        ulonglong2 w1r = ldg2x64(wp + HID);
        ulonglong2 w2r = ldg2x64(wp + 2 * HID);
        ulonglong2 w3r = ldg2x64(wp + 3 * HID);
#pragma unroll
        for (int e = 0; e < 4; ++e) {
            const float* ap = &sH1d[w][e][i4 * 8];
            ulonglong2 a01 = *(const ulonglong2*)(ap);
            ulonglong2 a23 = *(const ulonglong2*)(ap + 4);
            FMA2_STEP(cA[e], cB[e], a01, a23, w0, w1r, w2r, w3r)
        }
    }

    float4 b2v  = ldg4(b2 + ch);
    float4 g2v  = ldg4(g2 + ch);
    float4 be2v = ldg4(be2 + ch);
#pragma unroll
    for (int e = 0; e < 4; ++e) {
        float4 v;
        unpack2(cA[e], v.x, v.y);
        unpack2(cB[e], v.z, v.w);
        v.x += b2v.x; v.y += b2v.y; v.z += b2v.z; v.w += b2v.w;
        float4 o = ln_relu(v, g2v, be2v);
        long eg = base + w * 4 + e;
        int  s  = eidx[eg];                 // src node
        float* dp = g_sum + (long)s * HID + ch;
        atomicAdd(dp + 0, o.x);
        atomicAdd(dp + 1, o.y);
        atomicAdd(dp + 2, o.z);
        atomicAdd(dp + 3, o.w);
        if (lane == 0) atomicAdd(&g_cnt[s], 1.0f);
    }
}

// ---------------- kernel 2: mean + GRUCell ----------------
// block = 384 threads (one per gate-row j of 3H), 8 nodes per block.
// f32x2 pairing over k (both operands naturally contiguous); lanes hold
// even/odd partial sums, combined at the end.
__global__ void __launch_bounds__(384) gru_k(
    const float* __restrict__ hprev,
    const float* __restrict__ Wih, const float* __restrict__ bih,
    const float* __restrict__ Whh, const float* __restrict__ bhh)
{
    __shared__ float sA[8][HID];
    __shared__ float sH[8][HID];
    __shared__ float sR[8][HID];
    __shared__ float sZ[8][HID];

    const int tid = threadIdx.x;
    const long node0 = (long)blockIdx.x * 8;

    for (int idx = tid; idx < 8 * HID; idx += 384) {
        int n = idx >> 7, k = idx & 127;
        long g = (node0 + n) * HID + k;
        float c = g_cnt[node0 + n];
        sA[n][k] = g_sum[g] / fmaxf(c, 1.0f);   // scatter-mean
        sH[n][k] = hprev[g];
    }
    __syncthreads();

    const int j = tid;                    // 0..383 : gate row (r|z|n)
    unsigned long long gx2[8], gh2[8];
#pragma unroll
    for (int n = 0; n < 8; ++n) { gx2[n] = 0ull; gh2[n] = 0ull; }

    const float* wi = Wih + (long)j * HID;
    const float* wh = Whh + (long)j * HID;
#pragma unroll 4
    for (int k4 = 0; k4 < HID / 4; ++k4) {
        ulonglong2 wi2 = ldg2x64(wi + k4 * 4);
        ulonglong2 wh2 = ldg2x64(wh + k4 * 4);
#pragma unroll
        for (int n = 0; n < 8; ++n) {
            ulonglong2 a2 = *(const ulonglong2*)&sA[n][k4 * 4];
            ulonglong2 h2 = *(const ulonglong2*)&sH[n][k4 * 4];
            gx2[n] = fma2(a2.x, wi2.x, gx2[n]);
            gx2[n] = fma2(a2.y, wi2.y, gx2[n]);
            gh2[n] = fma2(h2.x, wh2.x, gh2[n]);
            gh2[n] = fma2(h2.y, wh2.y, gh2[n]);
        }
    }

    float gx[8], gh[8];
    const float bi = __ldg(bih + j), bh = __ldg(bhh + j);
#pragma unroll
    for (int n = 0; n < 8; ++n) {
        float lo, hi;
        unpack2(gx2[n], lo, hi); gx[n] = bi + lo + hi;
        unpack2(gh2[n], lo, hi); gh[n] = bh + lo + hi;
    }

    if (j < HID) {
#pragma unroll
        for (int n = 0; n < 8; ++n)
            sR[n][j] = 1.0f / (1.0f + expf(-(gx[n] + gh[n])));
    } else if (j < 2 * HID) {
        int jj = j - HID;
#pragma unroll
        for (int n = 0; n < 8; ++n)
            sZ[n][jj] = 1.0f / (1.0f + expf(-(gx[n] + gh[n])));
    }
    __syncthreads();
    if (j >= 2 * HID) {
        int jj = j - 2 * HID;
#pragma unroll
        for (int n = 0; n < 8; ++n) {
            float r  = sR[n][jj];
            float nn = tanhf(gx[n] + r * gh[n]);
            float z  = sZ[n][jj];
            g_hnew[(node0 + n) * HID + jj] = (1.0f - z) * nn + z * sH[n][jj];
        }
    }
}

// ---------------- kernel 3: gather + concat + classifier ----------------
// block = 128 threads = 4 warps; 4 edges/warp; duplicated activations in smem.
__global__ void __launch_bounds__(128) cls_k(
    const float* __restrict__ ea, const int* __restrict__ eidx,
    const float* __restrict__ Wc1, const float* __restrict__ bc1,
    const float* __restrict__ Wc2, const float* __restrict__ bc2,
    float* __restrict__ out)
{
    __shared__ float sRep[4][4][2 * (2 * HID + EDIM)];   // 576 floats/edge, 36.9 KB

    const int tid  = threadIdx.x;
    const int w    = tid >> 5;
    const int lane = tid & 31;
    const int ch   = lane * 4;
    const long base = (long)blockIdx.x * 16;

#pragma unroll
    for (int e = 0; e < 4; ++e) {
        long eg = base + w * 4 + e;
        int  s  = eidx[eg];
        int  d  = eidx[N_EDGES + eg];
        float4 vs = *(const float4*)(g_hnew + (long)s * HID + ch);
        float4 vd = *(const float4*)(g_hnew + (long)d * HID + ch);
        float* dp0 = &sRep[w][e][2 * ch];
        *(float4*)(dp0)     = make_float4(vs.x, vs.x, vs.y, vs.y);
        *(float4*)(dp0 + 4) = make_float4(vs.z, vs.z, vs.w, vs.w);
        float* dp1 = &sRep[w][e][2 * (HID + ch)];
        *(float4*)(dp1)     = make_float4(vd.x, vd.x, vd.y, vd.y);
        *(float4*)(dp1 + 4) = make_float4(vd.z, vd.z, vd.w, vd.w);
        if (lane < 8) {
            float4 va = *(const float4*)(ea + eg * EDIM + lane * 4);
            float* dp2 = &sRep[w][e][2 * (2 * HID + lane * 4)];
            *(float4*)(dp2)     = make_float4(va.x, va.x, va.y, va.y);
            *(float4*)(dp2 + 4) = make_float4(va.z, va.z, va.w, va.w);
        }
    }
    __syncwarp();

    unsigned long long aA[4], aB[4];
#pragma unroll
    for (int e = 0; e < 4; ++e) { aA[e] = 0ull; aB[e] = 0ull; }

#pragma unroll 8
    for (int i4 = 0; i4 < (2 * HID + EDIM) / 4; ++i4) {   // 72 iters
        const float* wp = Wc1 + (i4 * 4) * HID + ch;
        ulonglong2 w0  = ldg2x64(wp);
        ulonglong2 w1r = ldg2x64(wp + HID);
        ulonglong2 w2r = ldg2x64(wp + 2 * HID);
        ulonglong2 w3r = ldg2x64(wp + 3 * HID);
#pragma unroll
        for (int e = 0; e < 4; ++e) {
            const float* ap = &sRep[w][e][i4 * 8];
            ulonglong2 a01 = *(const ulonglong2*)(ap);
            ulonglong2 a23 = *(const ulonglong2*)(ap + 4);
            FMA2_STEP(aA[e], aB[e], a01, a23, w0, w1r, w2r, w3r)
        }
    }

    float4 bc1v = ldg4(bc1 + ch);
    float4 wc2v = ldg4(Wc2 + ch);
    const float bb = __ldg(bc2);
#pragma unroll
    for (int e = 0; e < 4; ++e) {
        float c0, c1, c2, c3;
        unpack2(aA[e], c0, c1);
        unpack2(aB[e], c2, c3);
        float t0 = fmaxf(c0 + bc1v.x, 0.0f);
        float t1 = fmaxf(c1 + bc1v.y, 0.0f);
        float t2 = fmaxf(c2 + bc1v.z, 0.0f);
        float t3 = fmaxf(c3 + bc1v.w, 0.0f);
        float p = t0 * wc2v.x + t1 * wc2v.y + t2 * wc2v.z + t3 * wc2v.w;
#pragma unroll
        for (int o = 16; o > 0; o >>= 1) p += __shfl_xor_sync(0xffffffffu, p, o);
        if (lane == 0) out[base + w * 4 + e] = p + bb;
    }
}

// ---------------- launch ----------------
extern "C" void kernel_launch(void* const* d_in, const int* in_sizes, int n_in,
                              void* d_out, int out_size)
{
    (void)in_sizes; (void)n_in; (void)out_size;
    // 0:x 1:edge_index 2:edge_attr 3:h_prev 4:W1 5:b1 6:g1 7:be1
    // 8:W2 9:b2 10:g2 11:be2 12:Wih 13:bih 14:Whh 15:bhh 16:Wc1 17:bc1 18:Wc2 19:bc2
    const int*   eidx  = (const int*)  d_in[1];
    const float* ea    = (const float*)d_in[2];
    const float* hprev = (const float*)d_in[3];
    const float* W1 = (const float*)d_in[4];
    const float* b1 = (const float*)d_in[5];
    const float* g1 = (const float*)d_in[6];
    const float* be1= (const float*)d_in[7];
    const float* W2 = (const float*)d_in[8];
    const float* b2 = (const float*)d_in[9];
    const float* g2 = (const float*)d_in[10];
    const float* be2= (const float*)d_in[11];
    const float* Wih= (const float*)d_in[12];
    const float* bih= (const float*)d_in[13];
    const float* Whh= (const float*)d_in[14];
    const float* bhh= (const float*)d_in[15];
    const float* Wc1= (const float*)d_in[16];
    const float* bc1= (const float*)d_in[17];
    const float* Wc2= (const float*)d_in[18];
    const float* bc2= (const float*)d_in[19];
    float* out = (float*)d_out;

    zero_k<<<(N_NODES * HID + 255) / 256, 256>>>();
    enc_scatter_k<<<N_EDGES / 16, 128>>>(ea, eidx, W1, b1, g1, be1, W2, b2, g2, be2);
    gru_k<<<N_NODES / 8, 384>>>(hprev, Wih, bih, Whh, bhh);
    cls_k<<<N_EDGES / 16, 128>>>(ea, eidx, Wc1, bc1, Wc2, bc2, out);
}

// round 7
// speedup vs baseline: 1.3348x; 1.3348x over previous
#include <cuda_runtime.h>

#define N_NODES 50000
#define N_EDGES 500000
#define HID 128
#define EDIM 32

// ---------------- scratch (device globals: no allocation allowed) ----------------
__device__ float g_sum [N_NODES * HID];   // scatter-sum of encoded edges
__device__ float g_cnt [N_NODES];         // per-node edge counts
__device__ float g_hnew[N_NODES * HID];   // GRU output

// ---------------- zero scratch ----------------
__global__ void zero_k() {
    int i = blockIdx.x * blockDim.x + threadIdx.x;
    if (i < N_NODES * HID) g_sum[i] = 0.0f;
    if (i < N_NODES)       g_cnt[i] = 0.0f;
}

// ---------------- packed fp32x2 helpers (sm_100a FFMA2) ----------------
__device__ __forceinline__ unsigned long long fma2(unsigned long long a,
                                                   unsigned long long b,
                                                   unsigned long long c) {
    unsigned long long d;
    asm("fma.rn.f32x2 %0, %1, %2, %3;" : "=l"(d) : "l"(a), "l"(b), "l"(c));
    return d;
}
__device__ __forceinline__ unsigned long long dup2(float x) {
    unsigned int xi = __float_as_uint(x);
    unsigned long long d;
    asm("mov.b64 %0, {%1, %1};" : "=l"(d) : "r"(xi));
    return d;
}
__device__ __forceinline__ void unpack2(unsigned long long v, float& lo, float& hi) {
    asm("mov.b64 {%0, %1}, %2;" : "=f"(lo), "=f"(hi) : "l"(v));
}

__device__ __forceinline__ float4 ldg4(const float* p) {
    return __ldg((const float4*)p);
}
__device__ __forceinline__ ulonglong2 ldg2x64(const float* p) {
    return __ldg((const ulonglong2*)p);
}

// LayerNorm(128) + affine + ReLU; lane holds channels lane*4..lane*4+3.
__device__ __forceinline__ float4 ln_relu(float4 v, float4 g, float4 b) {
    float s = v.x + v.y + v.z + v.w;
    float q = v.x * v.x + v.y * v.y + v.z * v.z + v.w * v.w;
#pragma unroll
    for (int o = 16; o > 0; o >>= 1) {
        s += __shfl_xor_sync(0xffffffffu, s, o);
        q += __shfl_xor_sync(0xffffffffu, q, o);
    }
    float mu   = s * (1.0f / 128.0f);
    float var  = q * (1.0f / 128.0f) - mu * mu;
    float rstd = rsqrtf(var + 1e-5f);
    float4 r;
    r.x = fmaxf((v.x - mu) * rstd * g.x + b.x, 0.0f);
    r.y = fmaxf((v.y - mu) * rstd * g.y + b.y, 0.0f);
    r.z = fmaxf((v.z - mu) * rstd * g.z + b.z, 0.0f);
    r.w = fmaxf((v.w - mu) * rstd * g.w + b.w, 0.0f);
    return r;
}

// 4 k-rows x 4 output channels for one edge: activations packed in registers.
#define FMA2_STEP4(AccA, AccB, A4, W0, W1r, W2r, W3r)                  \
    {                                                                   \
        unsigned long long _a0 = dup2(A4.x), _a1 = dup2(A4.y);          \
        unsigned long long _a2 = dup2(A4.z), _a3 = dup2(A4.w);          \
        AccA = fma2(_a0, W0.x,  AccA); AccB = fma2(_a0, W0.y,  AccB);   \
        AccA = fma2(_a1, W1r.x, AccA); AccB = fma2(_a1, W1r.y, AccB);   \
        AccA = fma2(_a2, W2r.x, AccA); AccB = fma2(_a2, W2r.y, AccB);   \
        AccA = fma2(_a3, W3r.x, AccA); AccB = fma2(_a3, W3r.y, AccB);   \
    }

// ---------------- kernel 1: edge encoder (Lin-LN-ReLU x2) + scatter-add ----------
// block = 128 threads = 4 warps; 8 edges/warp; 32 edges/block.
__global__ void __launch_bounds__(128) enc_scatter_k(
    const float* __restrict__ ea, const int* __restrict__ eidx,
    const float* __restrict__ W1, const float* __restrict__ b1,
    const float* __restrict__ g1, const float* __restrict__ be1,
    const float* __restrict__ W2, const float* __restrict__ b2,
    const float* __restrict__ g2, const float* __restrict__ be2)
{
    __shared__ float sEA[32 * EDIM];        // 4 KB raw edge_attr tile
    __shared__ float sH1[4][8][HID];        // 16 KB post-LN hidden

    const int tid  = threadIdx.x;
    const int w    = tid >> 5;
    const int lane = tid & 31;
    const int ch   = lane * 4;
    const long base = (long)blockIdx.x * 32;

    // cooperative coalesced load of 32 edges x 32 attrs
    ((float4*)sEA)[tid]       = ((const float4*)(ea + base * EDIM))[tid];
    ((float4*)sEA)[tid + 128] = ((const float4*)(ea + base * EDIM))[tid + 128];
    __syncthreads();

    // ---- layer 1: [8 edges,32] @ W1[32,128] ----
    unsigned long long aA[8], aB[8];
#pragma unroll
    for (int e = 0; e < 8; ++e) { aA[e] = 0ull; aB[e] = 0ull; }

#pragma unroll 4
    for (int i4 = 0; i4 < EDIM / 4; ++i4) {
        const float* wp = W1 + (i4 * 4) * HID + ch;
        ulonglong2 w0  = ldg2x64(wp);
        ulonglong2 w1r = ldg2x64(wp + HID);
        ulonglong2 w2r = ldg2x64(wp + 2 * HID);
        ulonglong2 w3r = ldg2x64(wp + 3 * HID);
#pragma unroll
        for (int e = 0; e < 8; ++e) {
            float4 a = *(const float4*)(sEA + (w * 8 + e) * EDIM + i4 * 4);
            FMA2_STEP4(aA[e], aB[e], a, w0, w1r, w2r, w3r)
        }
    }

    float4 b1v  = ldg4(b1 + ch);
    float4 g1v  = ldg4(g1 + ch);
    float4 be1v = ldg4(be1 + ch);
#pragma unroll
    for (int e = 0; e < 8; ++e) {
        float4 v;
        unpack2(aA[e], v.x, v.y);
        unpack2(aB[e], v.z, v.w);
        v.x += b1v.x; v.y += b1v.y; v.z += b1v.z; v.w += b1v.w;
        *(float4*)&sH1[w][e][ch] = ln_relu(v, g1v, be1v);
    }
    __syncwarp();

    // ---- layer 2: [8 edges,128] @ W2[128,128] ----
    unsigned long long cA[8], cB[8];
#pragma unroll
    for (int e = 0; e < 8; ++e) { cA[e] = 0ull; cB[e] = 0ull; }

#pragma unroll 4
    for (int i4 = 0; i4 < HID / 4; ++i4) {
        const float* wp = W2 + (i4 * 4) * HID + ch;
        ulonglong2 w0  = ldg2x64(wp);
        ulonglong2 w1r = ldg2x64(wp + HID);
        ulonglong2 w2r = ldg2x64(wp + 2 * HID);
        ulonglong2 w3r = ldg2x64(wp + 3 * HID);
#pragma unroll
        for (int e = 0; e < 8; ++e) {
            float4 a = *(const float4*)&sH1[w][e][i4 * 4];
            FMA2_STEP4(cA[e], cB[e], a, w0, w1r, w2r, w3r)
        }
    }

    float4 b2v  = ldg4(b2 + ch);
    float4 g2v  = ldg4(g2 + ch);
    float4 be2v = ldg4(be2 + ch);
#pragma unroll
    for (int e = 0; e < 8; ++e) {
        float4 v;
        unpack2(cA[e], v.x, v.y);
        unpack2(cB[e], v.z, v.w);
        v.x += b2v.x; v.y += b2v.y; v.z += b2v.z; v.w += b2v.w;
        float4 o = ln_relu(v, g2v, be2v);
        long eg = base + w * 8 + e;
        int  s  = eidx[eg];                 // src node
        float* dp = g_sum + (long)s * HID + ch;
        atomicAdd(dp + 0, o.x);
        atomicAdd(dp + 1, o.y);
        atomicAdd(dp + 2, o.z);
        atomicAdd(dp + 3, o.w);
        if (lane == 0) atomicAdd(&g_cnt[s], 1.0f);
    }
}

// ---------------- kernel 2: mean + GRUCell ----------------
// block = 384 threads (one per gate-row j of 3H), 8 nodes per block.
// f32x2 pairing over k (both operands naturally contiguous).
__global__ void __launch_bounds__(384) gru_k(
    const float* __restrict__ hprev,
    const float* __restrict__ Wih, const float* __restrict__ bih,
    const float* __restrict__ Whh, const float* __restrict__ bhh)
{
    __shared__ float sA[8][HID];
    __shared__ float sH[8][HID];
    __shared__ float sR[8][HID];
    __shared__ float sZ[8][HID];

    const int tid = threadIdx.x;
    const long node0 = (long)blockIdx.x * 8;

    for (int idx = tid; idx < 8 * HID; idx += 384) {
        int n = idx >> 7, k = idx & 127;
        long g = (node0 + n) * HID + k;
        float c = g_cnt[node0 + n];
        sA[n][k] = g_sum[g] / fmaxf(c, 1.0f);   // scatter-mean
        sH[n][k] = hprev[g];
    }
    __syncthreads();

    const int j = tid;                    // 0..383 : gate row (r|z|n)
    unsigned long long gx2[8], gh2[8];
#pragma unroll
    for (int n = 0; n < 8; ++n) { gx2[n] = 0ull; gh2[n] = 0ull; }

    const float* wi = Wih + (long)j * HID;
    const float* wh = Whh + (long)j * HID;
#pragma unroll 4
    for (int k4 = 0; k4 < HID / 4; ++k4) {
        ulonglong2 wi2 = ldg2x64(wi + k4 * 4);
        ulonglong2 wh2 = ldg2x64(wh + k4 * 4);
#pragma unroll
        for (int n = 0; n < 8; ++n) {
            ulonglong2 a2 = *(const ulonglong2*)&sA[n][k4 * 4];
            ulonglong2 h2 = *(const ulonglong2*)&sH[n][k4 * 4];
            gx2[n] = fma2(a2.x, wi2.x, gx2[n]);
            gx2[n] = fma2(a2.y, wi2.y, gx2[n]);
            gh2[n] = fma2(h2.x, wh2.x, gh2[n]);
            gh2[n] = fma2(h2.y, wh2.y, gh2[n]);
        }
    }

    float gx[8], gh[8];
    const float bi = __ldg(bih + j), bh = __ldg(bhh + j);
#pragma unroll
    for (int n = 0; n < 8; ++n) {
        float lo, hi;
        unpack2(gx2[n], lo, hi); gx[n] = bi + lo + hi;
        unpack2(gh2[n], lo, hi); gh[n] = bh + lo + hi;
    }

    if (j < HID) {
#pragma unroll
        for (int n = 0; n < 8; ++n)
            sR[n][j] = 1.0f / (1.0f + expf(-(gx[n] + gh[n])));
    } else if (j < 2 * HID) {
        int jj = j - HID;
#pragma unroll
        for (int n = 0; n < 8; ++n)
            sZ[n][jj] = 1.0f / (1.0f + expf(-(gx[n] + gh[n])));
    }
    __syncthreads();
    if (j >= 2 * HID) {
        int jj = j - 2 * HID;
#pragma unroll
        for (int n = 0; n < 8; ++n) {
            float r  = sR[n][jj];
            float nn = tanhf(gx[n] + r * gh[n]);
            float z  = sZ[n][jj];
            g_hnew[(node0 + n) * HID + jj] = (1.0f - z) * nn + z * sH[n][jj];
        }
    }
}

// ---------------- kernel 3: gather + concat + classifier ----------------
// block = 128 threads = 4 warps; 8 edges/warp; 32 edges/block.
__global__ void __launch_bounds__(128) cls_k(
    const float* __restrict__ ea, const int* __restrict__ eidx,
    const float* __restrict__ Wc1, const float* __restrict__ bc1,
    const float* __restrict__ Wc2, const float* __restrict__ bc2,
    float* __restrict__ out)
{
    __shared__ float sRep[4][8][2 * HID + EDIM];   // 288 floats/edge, 36.9 KB

    const int tid  = threadIdx.x;
    const int w    = tid >> 5;
    const int lane = tid & 31;
    const int ch   = lane * 4;
    const long base = (long)blockIdx.x * 32;

#pragma unroll
    for (int e = 0; e < 8; ++e) {
        long eg = base + w * 8 + e;
        int  s  = eidx[eg];
        int  d  = eidx[N_EDGES + eg];
        *(float4*)&sRep[w][e][ch]       = *(const float4*)(g_hnew + (long)s * HID + ch);
        *(float4*)&sRep[w][e][HID + ch] = *(const float4*)(g_hnew + (long)d * HID + ch);
        if (lane < 8)
            *(float4*)&sRep[w][e][2 * HID + lane * 4] =
                *(const float4*)(ea + eg * EDIM + lane * 4);
    }
    __syncwarp();

    unsigned long long aA[8], aB[8];
#pragma unroll
    for (int e = 0; e < 8; ++e) { aA[e] = 0ull; aB[e] = 0ull; }

#pragma unroll 4
    for (int i4 = 0; i4 < (2 * HID + EDIM) / 4; ++i4) {   // 72 iters
        const float* wp = Wc1 + (i4 * 4) * HID + ch;
        ulonglong2 w0  = ldg2x64(wp);
        ulonglong2 w1r = ldg2x64(wp + HID);
        ulonglong2 w2r = ldg2x64(wp + 2 * HID);
        ulonglong2 w3r = ldg2x64(wp + 3 * HID);
#pragma unroll
        for (int e = 0; e < 8; ++e) {
            float4 a = *(const float4*)&sRep[w][e][i4 * 4];
            FMA2_STEP4(aA[e], aB[e], a, w0, w1r, w2r, w3r)
        }
    }

    float4 bc1v = ldg4(bc1 + ch);
    float4 wc2v = ldg4(Wc2 + ch);
    const float bb = __ldg(bc2);
#pragma unroll
    for (int e = 0; e < 8; ++e) {
        float c0, c1, c2, c3;
        unpack2(aA[e], c0, c1);
        unpack2(aB[e], c2, c3);
        float t0 = fmaxf(c0 + bc1v.x, 0.0f);
        float t1 = fmaxf(c1 + bc1v.y, 0.0f);
        float t2 = fmaxf(c2 + bc1v.z, 0.0f);
        float t3 = fmaxf(c3 + bc1v.w, 0.0f);
        float p = t0 * wc2v.x + t1 * wc2v.y + t2 * wc2v.z + t3 * wc2v.w;
#pragma unroll
        for (int o = 16; o > 0; o >>= 1) p += __shfl_xor_sync(0xffffffffu, p, o);
        if (lane == 0) out[base + w * 8 + e] = p + bb;
    }
}

// ---------------- launch ----------------
extern "C" void kernel_launch(void* const* d_in, const int* in_sizes, int n_in,
                              void* d_out, int out_size)
{
    (void)in_sizes; (void)n_in; (void)out_size;
    // 0:x 1:edge_index 2:edge_attr 3:h_prev 4:W1 5:b1 6:g1 7:be1
    // 8:W2 9:b2 10:g2 11:be2 12:Wih 13:bih 14:Whh 15:bhh 16:Wc1 17:bc1 18:Wc2 19:bc2
    const int*   eidx  = (const int*)  d_in[1];
    const float* ea    = (const float*)d_in[2];
    const float* hprev = (const float*)d_in[3];
    const float* W1 = (const float*)d_in[4];
    const float* b1 = (const float*)d_in[5];
    const float* g1 = (const float*)d_in[6];
    const float* be1= (const float*)d_in[7];
    const float* W2 = (const float*)d_in[8];
    const float* b2 = (const float*)d_in[9];
    const float* g2 = (const float*)d_in[10];
    const float* be2= (const float*)d_in[11];
    const float* Wih= (const float*)d_in[12];
    const float* bih= (const float*)d_in[13];
    const float* Whh= (const float*)d_in[14];
    const float* bhh= (const float*)d_in[15];
    const float* Wc1= (const float*)d_in[16];
    const float* bc1= (const float*)d_in[17];
    const float* Wc2= (const float*)d_in[18];
    const float* bc2= (const float*)d_in[19];
    float* out = (float*)d_out;

    zero_k<<<(N_NODES * HID + 255) / 256, 256>>>();
    enc_scatter_k<<<N_EDGES / 32, 128>>>(ea, eidx, W1, b1, g1, be1, W2, b2, g2, be2);
    gru_k<<<N_NODES / 8, 384>>>(hprev, Wih, bih, Whh, bhh);
    cls_k<<<N_EDGES / 32, 128>>>(ea, eidx, Wc1, bc1, Wc2, bc2, out);
}